// round 10
// baseline (speedup 1.0000x reference)
#include <cuda_runtime.h>
#include <cuda_fp16.h>
#include <cstdint>

#define D      150
#define Dp     160
#define NTOT   25600     // Dp*Dp, n = j*160 + i
#define BZ     256
#define DIN    1024
#define INV2048 4.8828125e-4f

// ---------------- scratch (__device__ globals; zero-init; pads never written)
__device__ __align__(16) float g_emb[3][BZ][Dp];
__device__ __align__(16) __half g_eh[3][BZ][Dp];      // emb hi image (fp16)
__device__ __align__(16) __half g_el[3][BZ][Dp];      // emb lo image (x2048)
__device__ __align__(16) __half g_tbh[6][NTOT][Dp];   // T image [q][n][k] hi
__device__ __align__(16) __half g_tbl[6][NTOT][Dp];   // lo (x2048)
__device__ __align__(16) __half g_wbh[6][BZ][Dp][Dp]; // w image [q][bz][j][i] hi
__device__ __align__(16) __half g_wbl[6][BZ][Dp][Dp]; // lo (x2048)
__device__ __align__(16) float g_cp[4][128][128][128];// co-parent staging

// q0 span_psh (no sym)  q1 span_pst (sym)  q2 ph_sib  q3 pt_sib
// q4 ph_cop  q5 pt_cop  (q4,q5 permuted out via g_cp + k_cop)
__constant__ int c_ZI[6] = {2,2,2,2,0,1};
__constant__ int c_XI[6] = {0,0,0,1,2,2};
__constant__ int c_YI[6] = {1,1,0,1,2,2};

// ---------------- low-level helpers ----------------------------------------
__device__ __forceinline__ uint32_t smem_u32(const void* p){
    uint32_t a;
    asm("{ .reg .u64 t; cvta.to.shared.u64 t, %1; cvt.u32.u64 %0, t; }" : "=r"(a) : "l"(p));
    return a;
}
// fp16 split: hi = RN(a); lo = RN((a-hi)*2048)  (lo scaled into normal range)
__device__ __forceinline__ void split_pack(float a, float b, uint32_t& h, uint32_t& l){
    __half ah = __float2half_rn(a), bh = __float2half_rn(b);
    __half al = __float2half_rn((a - __half2float(ah)) * 2048.f);
    __half bl = __float2half_rn((b - __half2float(bh)) * 2048.f);
    h = (uint32_t)__half_as_ushort(ah) | ((uint32_t)__half_as_ushort(bh) << 16);
    l = (uint32_t)__half_as_ushort(al) | ((uint32_t)__half_as_ushort(bl) << 16);
}
__device__ __forceinline__ float2 h2f2(uint32_t u){
    __half2 v = *(__half2*)&u;
    return __half22float2(v);
}
// combine hh (f32 acc) + lo-corrections (f16 acc, scaled 2048)
__device__ __forceinline__ void comb4(const float* f, const uint32_t* h, float* o){
    float2 p0 = h2f2(h[0]), p1 = h2f2(h[1]);
    o[0] = f[0] + p0.x * INV2048;
    o[1] = f[1] + p0.y * INV2048;
    o[2] = f[2] + p1.x * INV2048;
    o[3] = f[3] + p1.y * INV2048;
}
// hh term: fp32 accumulate (full-rate precision path)
__device__ __forceinline__ void mma_f32(float* c, const uint32_t* a, uint32_t b0, uint32_t b1){
    asm volatile("mma.sync.aligned.m16n8k16.row.col.f32.f16.f16.f32 "
        "{%0,%1,%2,%3}, {%4,%5,%6,%7}, {%8,%9}, {%0,%1,%2,%3};"
        : "+f"(c[0]), "+f"(c[1]), "+f"(c[2]), "+f"(c[3])
        : "r"(a[0]), "r"(a[1]), "r"(a[2]), "r"(a[3]), "r"(b0), "r"(b1));
}
// lo terms: fp16 accumulate (2x-rate path)
__device__ __forceinline__ void mma_f16(uint32_t* c, const uint32_t* a, uint32_t b0, uint32_t b1){
    asm volatile("mma.sync.aligned.m16n8k16.row.col.f16.f16.f16.f16 "
        "{%0,%1}, {%2,%3,%4,%5}, {%6,%7}, {%0,%1};"
        : "+r"(c[0]), "+r"(c[1])
        : "r"(a[0]), "r"(a[1]), "r"(a[2]), "r"(a[3]), "r"(b0), "r"(b1));
}
__device__ __forceinline__ void ldsm4(uint32_t* r, uint32_t a){
    asm volatile("ldmatrix.sync.aligned.m8n8.x4.shared.b16 {%0,%1,%2,%3}, [%4];"
        : "=r"(r[0]), "=r"(r[1]), "=r"(r[2]), "=r"(r[3]) : "r"(a));
}
__device__ __forceinline__ void ldsm2(uint32_t* r, uint32_t a){
    asm volatile("ldmatrix.sync.aligned.m8n8.x2.shared.b16 {%0,%1}, [%2];"
        : "=r"(r[0]), "=r"(r[1]) : "r"(a));
}
__device__ __forceinline__ void cpa16(uint32_t s, const void* g){
    asm volatile("cp.async.cg.shared.global [%0], [%1], 16;" :: "r"(s), "l"(g));
}
#define CP_COMMIT() asm volatile("cp.async.commit_group;" ::: "memory")
#define CP_WAIT1()  asm volatile("cp.async.wait_group 1;" ::: "memory")
#define CP_WAIT0()  asm volatile("cp.async.wait_group 0;" ::: "memory")

// 64B-row layout (k32 chunks): 4x16B units/row, swizzle u ^ ((row>>1)&3)
__device__ __forceinline__ uint32_t swz64(int row, int u){
    return (uint32_t)(row * 64 + 16 * ((u ^ (row >> 1)) & 3));
}
__device__ __forceinline__ uint32_t a64(uint32_t base, int r0, int ln, int c){
    int g = ln >> 3;
    int row = r0 + ((g & 1) << 3) + (ln & 7);
    return base + swz64(row, 2 * c + (g >> 1));
}
__device__ __forceinline__ uint32_t a64_2(uint32_t base, int r0, int ln, int c){
    int row = r0 + (ln & 7);
    return base + swz64(row, 2 * c + ((ln >> 3) & 1));
}
// 320B-row image layout (v, Y)
__device__ __forceinline__ uint32_t voff(int row, int j){
    return (uint32_t)(row * 320 + 16 * ((j >> 3) ^ ((row >> 1) & 3)) + (j & 7) * 2);
}
__device__ __forceinline__ uint32_t vuoff(int row, int u){
    return (uint32_t)(row * 320 + 16 * (u ^ ((row >> 1) & 3)));
}
__device__ __forceinline__ uint32_t ldsV(uint32_t base, int r0, int ln, int u0){
    int g = ln >> 3;
    int row = r0 + ((g & 1) << 3) + (ln & 7);
    return base + vuoff(row, u0 + (g >> 1));
}

// ---------------- MLP -------------------------------------------------------
__global__ void k_mlp(const float* __restrict__ x,
                      const float* __restrict__ W0, const float* __restrict__ b0,
                      const float* __restrict__ W1, const float* __restrict__ b1,
                      const float* __restrict__ W2, const float* __restrict__ b2)
{
    int row = blockIdx.x, e = blockIdx.y;
    const float* W  = (e == 0) ? W0 : (e == 1) ? W1 : W2;
    const float* bb = (e == 0) ? b0 : (e == 1) ? b1 : b2;
    __shared__ float xs[DIN];
    int tid = threadIdx.x;
    for (int k = tid; k < DIN; k += 160) xs[k] = x[row * DIN + k];
    __syncthreads();
    if (tid < D) {
        float acc = bb[tid];
        #pragma unroll 8
        for (int k = 0; k < DIN; ++k) acc += xs[k] * W[k * D + tid];
        g_emb[e][row][tid] = (acc >= 0.f) ? acc : 0.1f * acc;
    }
}

// ---------------- emb -> split fp16 images ----------------------------------
__global__ void k_embimg()
{
    int idx = blockIdx.x * 256 + threadIdx.x;
    if (idx >= 3 * 256 * 80) return;
    int e = idx / 20480, rem = idx % 20480;
    int row = rem / 80, kp = rem % 80;
    uint32_t h, l;
    split_pack(g_emb[e][row][2*kp], g_emb[e][row][2*kp+1], h, l);
    *(uint32_t*)&g_eh[e][row][2*kp] = h;
    *(uint32_t*)&g_el[e][row][2*kp] = l;
}

// ---------------- T[i][k][j] -> TB[q][(j*160+i)][k] hi/lo -------------------
__global__ void k_timg(const float* __restrict__ T0, const float* __restrict__ T1,
                       const float* __restrict__ T2, const float* __restrict__ T3,
                       const float* __restrict__ T4, const float* __restrict__ T5)
{
    int q = blockIdx.z, i = blockIdx.y, j0 = blockIdx.x * 32;
    const float* T = (q==0)?T0:(q==1)?T1:(q==2)?T2:(q==3)?T3:(q==4)?T4:T5;
    __shared__ float ts[32][152];
    int tid = threadIdx.x;
    for (int t = tid; t < 150 * 32; t += 256) {
        int k = t >> 5, j = t & 31;
        if (j0 + j < D) ts[j][k] = T[(i * D + k) * D + j0 + j];
    }
    __syncthreads();
    for (int t = tid; t < 32 * 75; t += 256) {
        int j = t / 75, kp = t % 75;
        if (j0 + j < D) {
            uint32_t h, l;
            split_pack(ts[j][2*kp], ts[j][2*kp+1], h, l);
            int n = (j0 + j) * Dp + i;
            *(uint32_t*)&g_tbh[q][n][2*kp] = h;
            *(uint32_t*)&g_tbl[q][n][2*kp] = l;
        }
    }
}

// ---------------- stage A: w = Z . TB^T, k32 chunks, 512 thr ----------------
// CTA tile 128x128, warps 4m x 4n (32x32 tiles)
// slot (32KB): Ah@0 Al@8192 Bh@16384 Bl@24576; 128 rows x 64B each
__global__ void __launch_bounds__(512, 1) k_stageA()
{
    extern __shared__ __align__(16) unsigned char smA[];   // 3 x 32768
    uint32_t sb = smem_u32(smA);
    int q = blockIdx.z, m0 = blockIdx.y * 128, n0 = blockIdx.x * 128;
    int tid = threadIdx.x, w = tid >> 5, ln = tid & 31;
    int wm = w & 3, wn = w >> 2;
    int zi = c_ZI[q];

    // hoisted prefetch addressing: thread covers (row, u) of 4 arrays
    int pr = tid >> 2, pu = tid & 3;
    uint32_t sw0 = swz64(pr, pu);
    const __half* gpAh = &g_eh[zi][0][0]  + (size_t)(m0 + pr) * Dp + pu * 8;
    const __half* gpAl = &g_el[zi][0][0]  + (size_t)(m0 + pr) * Dp + pu * 8;
    const __half* gpBh = &g_tbh[q][0][0]  + (size_t)(n0 + pr) * Dp + pu * 8;
    const __half* gpBl = &g_tbl[q][0][0]  + (size_t)(n0 + pr) * Dp + pu * 8;

    float    accF[2][4][4];
    uint32_t accH[2][4][2];
    #pragma unroll
    for (int a = 0; a < 2; ++a)
        #pragma unroll
        for (int b = 0; b < 4; ++b) {
            #pragma unroll
            for (int c = 0; c < 4; ++c) accF[a][b][c] = 0.f;
            accH[a][b][0] = 0u; accH[a][b][1] = 0u;
        }

    #define PREF_A(slot, kc) do { \
        if ((kc) < Dp) { \
            uint32_t db = sb + (slot) * 32768 + sw0; \
            cpa16(db,         gpAh + (kc)); \
            cpa16(db +  8192, gpAl + (kc)); \
            cpa16(db + 16384, gpBh + (kc)); \
            cpa16(db + 24576, gpBl + (kc)); \
        } \
        CP_COMMIT(); \
    } while(0)

    PREF_A(0, 0);
    PREF_A(1, 32);
    for (int ks = 0; ks < 5; ++ks) {
        CP_WAIT1();
        __syncthreads();
        PREF_A((ks + 2) % 3, (ks + 2) * 32);
        uint32_t base = sb + (ks % 3) * 32768;
        #pragma unroll
        for (int c = 0; c < 2; ++c) {
            uint32_t ah[2][4], al[2][4];
            #pragma unroll
            for (int mt = 0; mt < 2; ++mt) {
                ldsm4(ah[mt], a64(base,        wm * 32 + mt * 16, ln, c));
                ldsm4(al[mt], a64(base + 8192, wm * 32 + mt * 16, ln, c));
            }
            uint32_t bh[4][2], bl[4][2];
            #pragma unroll
            for (int p = 0; p < 2; ++p) {
                uint32_t r4[4];
                ldsm4(r4, a64(base + 16384, wn * 32 + p * 16, ln, c));
                bh[2*p][0]=r4[0]; bh[2*p][1]=r4[2]; bh[2*p+1][0]=r4[1]; bh[2*p+1][1]=r4[3];
                ldsm4(r4, a64(base + 24576, wn * 32 + p * 16, ln, c));
                bl[2*p][0]=r4[0]; bl[2*p][1]=r4[2]; bl[2*p+1][0]=r4[1]; bl[2*p+1][1]=r4[3];
            }
            #pragma unroll
            for (int n8 = 0; n8 < 4; ++n8) {
                mma_f32(accF[0][n8], ah[0], bh[n8][0], bh[n8][1]);
                mma_f32(accF[1][n8], ah[1], bh[n8][0], bh[n8][1]);
            }
            #pragma unroll
            for (int n8 = 0; n8 < 4; ++n8) {
                mma_f16(accH[0][n8], ah[0], bl[n8][0], bl[n8][1]);
                mma_f16(accH[1][n8], ah[1], bl[n8][0], bl[n8][1]);
            }
            #pragma unroll
            for (int n8 = 0; n8 < 4; ++n8) {
                mma_f16(accH[0][n8], al[0], bh[n8][0], bh[n8][1]);
                mma_f16(accH[1][n8], al[1], bh[n8][0], bh[n8][1]);
            }
        }
    }
    #undef PREF_A

    __half* WH = &g_wbh[0][0][0][0];
    __half* WL = &g_wbl[0][0][0][0];
    int yb = 2 * (ln & 3);
    #pragma unroll
    for (int mt = 0; mt < 2; ++mt) {
        int mA = m0 + wm * 32 + mt * 16 + (ln >> 2);
        #pragma unroll
        for (int n8 = 0; n8 < 4; ++n8) {
            int n = n0 + wn * 32 + n8 * 8 + yb;
            float o[4]; comb4(accF[mt][n8], accH[mt][n8], o);
            size_t off0 = ((size_t)(q * BZ + mA)) * 25600 + n;
            size_t off1 = off0 + (size_t)8 * 25600;
            uint32_t h, l;
            split_pack(o[0], o[1], h, l);
            *(uint32_t*)(WH + off0) = h; *(uint32_t*)(WL + off0) = l;
            split_pack(o[2], o[3], h, l);
            *(uint32_t*)(WH + off1) = h; *(uint32_t*)(WL + off1) = l;
        }
    }
}

// ---------------- fused B+C per (q,bz): 512 threads, k32 chunks -------------
// slot (36864B): Xh@0 Xl@8192 (128x64B) ; Wh@16384 Wl@26624 (160x64B)
// dyn smem: [0,110592) 3 slots -> Y images [0,81920)
//           [110592,192512) v images; epilogue s-tile at [0,66560)
__global__ void __launch_bounds__(512, 1) k_fusedBC(float* __restrict__ out)
{
    extern __shared__ __align__(16) unsigned char dynsm[];
    uint32_t sb = smem_u32(dynsm);
    int q = blockIdx.y, bz = blockIdx.x, b = bz >> 7, z = bz & 127;
    int tid = threadIdx.x, w = tid >> 5, ln = tid & 31;
    int wm = w & 3, wn = w >> 2;        // 4 x 4

    const __half *Xh = &g_eh[c_XI[q]][b*128][0], *Xl = &g_el[c_XI[q]][b*128][0];
    const __half *Wh = &g_wbh[q][bz][0][0],      *Wl = &g_wbl[q][bz][0][0];
    const __half *Yh = &g_eh[c_YI[q]][b*128][0], *Yl = &g_el[c_YI[q]][b*128][0];

    // hoisted prefetch addressing
    int pr = tid >> 2, pu = tid & 3;
    uint32_t swX = swz64(pr, pu);
    const __half* gpXh = Xh + (size_t)pr * Dp + pu * 8;
    const __half* gpXl = Xl + (size_t)pr * Dp + pu * 8;
    const __half* gpW[3]; uint32_t dpW[3];
    int nW = (tid < 256) ? 3 : 2;
    #pragma unroll
    for (int i = 0; i < 3; ++i) {
        int t = tid + 512 * i;
        if (t < 1280) {
            int img = t / 640, r2 = t % 640;
            int row = r2 >> 2, u = r2 & 3;
            dpW[i] = 16384 + img * 10240 + swz64(row, u);
            gpW[i] = (img ? Wl : Wh) + (size_t)row * Dp + u * 8;
        } else { dpW[i] = 0; gpW[i] = Wh; }
    }

    #define PREF_B(slot, kc) do { \
        if ((kc) < Dp) { \
            uint32_t db = sb + (slot) * 36864; \
            cpa16(db + swX,        gpXh + (kc)); \
            cpa16(db + 8192 + swX, gpXl + (kc)); \
            _Pragma("unroll") \
            for (int i = 0; i < 3; ++i) \
                if (i < nW) cpa16(db + dpW[i], gpW[i] + (kc)); \
        } \
        CP_COMMIT(); \
    } while(0)

    // ---- stage B (warp tile 32x40)
    float    accBF[2][5][4];
    uint32_t accBH[2][5][2];
    #pragma unroll
    for (int mt = 0; mt < 2; ++mt)
        #pragma unroll
        for (int i = 0; i < 5; ++i) {
            #pragma unroll
            for (int c = 0; c < 4; ++c) accBF[mt][i][c] = 0.f;
            accBH[mt][i][0] = 0u; accBH[mt][i][1] = 0u;
        }

    PREF_B(0, 0);
    PREF_B(1, 32);
    for (int ks = 0; ks < 5; ++ks) {
        CP_WAIT1();
        __syncthreads();
        PREF_B((ks + 2) % 3, (ks + 2) * 32);
        uint32_t base = sb + (ks % 3) * 36864;
        #pragma unroll
        for (int c = 0; c < 2; ++c) {
            uint32_t ah[2][4], al[2][4];
            #pragma unroll
            for (int mt = 0; mt < 2; ++mt) {
                ldsm4(ah[mt], a64(base,        wm * 32 + mt * 16, ln, c));
                ldsm4(al[mt], a64(base + 8192, wm * 32 + mt * 16, ln, c));
            }
            uint32_t bh[5][2], bl[5][2];
            #pragma unroll
            for (int p = 0; p < 2; ++p) {
                uint32_t r4[4];
                ldsm4(r4, a64(base + 16384, wn * 40 + p * 16, ln, c));
                bh[2*p][0]=r4[0]; bh[2*p][1]=r4[2]; bh[2*p+1][0]=r4[1]; bh[2*p+1][1]=r4[3];
                ldsm4(r4, a64(base + 26624, wn * 40 + p * 16, ln, c));
                bl[2*p][0]=r4[0]; bl[2*p][1]=r4[2]; bl[2*p+1][0]=r4[1]; bl[2*p+1][1]=r4[3];
            }
            {
                uint32_t r2[2];
                ldsm2(r2, a64_2(base + 16384, wn * 40 + 32, ln, c));
                bh[4][0]=r2[0]; bh[4][1]=r2[1];
                ldsm2(r2, a64_2(base + 26624, wn * 40 + 32, ln, c));
                bl[4][0]=r2[0]; bl[4][1]=r2[1];
            }
            #pragma unroll
            for (int n8 = 0; n8 < 5; ++n8) {
                mma_f32(accBF[0][n8], ah[0], bh[n8][0], bh[n8][1]);
                mma_f32(accBF[1][n8], ah[1], bh[n8][0], bh[n8][1]);
            }
            #pragma unroll
            for (int n8 = 0; n8 < 5; ++n8) {
                mma_f16(accBH[0][n8], ah[0], bl[n8][0], bl[n8][1]);
                mma_f16(accBH[1][n8], ah[1], bl[n8][0], bl[n8][1]);
            }
            #pragma unroll
            for (int n8 = 0; n8 < 5; ++n8) {
                mma_f16(accBH[0][n8], al[0], bh[n8][0], bh[n8][1]);
                mma_f16(accBH[1][n8], al[1], bh[n8][0], bh[n8][1]);
            }
        }
    }
    #undef PREF_B
    __syncthreads();   // stage-B reads done; slot region free for Y images

    // ---- Y prefetch into [0,81920), overlapped with v writes
    for (int t = tid; t < 5120; t += 512) {
        int img = t / 2560, r2 = t % 2560;
        int r = r2 / 20, u = r2 % 20;
        uint32_t dst = sb + img * 40960 + vuoff(r, u);
        const __half* g = (img ? Yl : Yh) + (size_t)r * Dp + u * 8;
        cpa16(dst, g);
    }
    CP_COMMIT();

    // ---- v (combine) -> split-fp16 smem images at [110592,192512)
    #pragma unroll
    for (int mt = 0; mt < 2; ++mt) {
        #pragma unroll
        for (int n8 = 0; n8 < 5; ++n8) {
            int j  = wn * 40 + n8 * 8 + 2 * (ln & 3);
            int x1 = wm * 32 + mt * 16 + (ln >> 2);
            float o[4]; comb4(accBF[mt][n8], accBH[mt][n8], o);
            uint32_t h, l;
            split_pack(o[0], o[1], h, l);
            *(uint32_t*)(dynsm + 110592 + voff(x1, j)) = h;
            *(uint32_t*)(dynsm + 151552 + voff(x1, j)) = l;
            split_pack(o[2], o[3], h, l);
            *(uint32_t*)(dynsm + 110592 + voff(x1 + 8, j)) = h;
            *(uint32_t*)(dynsm + 151552 + voff(x1 + 8, j)) = l;
        }
    }
    CP_WAIT0();
    __syncthreads();

    // ---- stage C (warp tile 32x32; pure ldsm+mma from images)
    float    accCF[2][4][4];
    uint32_t accCH[2][4][2];
    #pragma unroll
    for (int mt = 0; mt < 2; ++mt)
        #pragma unroll
        for (int i = 0; i < 4; ++i) {
            #pragma unroll
            for (int c = 0; c < 4; ++c) accCF[mt][i][c] = 0.f;
            accCH[mt][i][0] = 0u; accCH[mt][i][1] = 0u;
        }

    #pragma unroll
    for (int kk = 0; kk < 10; ++kk) {
        int u0 = kk * 2;
        uint32_t ah[2][4], al[2][4];
        #pragma unroll
        for (int mt = 0; mt < 2; ++mt) {
            ldsm4(ah[mt], ldsV(sb + 110592, wm * 32 + mt * 16, ln, u0));
            ldsm4(al[mt], ldsV(sb + 151552, wm * 32 + mt * 16, ln, u0));
        }
        uint32_t bh[4][2], bl[4][2];
        #pragma unroll
        for (int p = 0; p < 2; ++p) {
            uint32_t r4[4];
            ldsm4(r4, ldsV(sb,         wn * 32 + p * 16, ln, u0));
            bh[2*p][0]=r4[0]; bh[2*p][1]=r4[2]; bh[2*p+1][0]=r4[1]; bh[2*p+1][1]=r4[3];
            ldsm4(r4, ldsV(sb + 40960, wn * 32 + p * 16, ln, u0));
            bl[2*p][0]=r4[0]; bl[2*p][1]=r4[2]; bl[2*p+1][0]=r4[1]; bl[2*p+1][1]=r4[3];
        }
        #pragma unroll
        for (int n8 = 0; n8 < 4; ++n8) {
            mma_f32(accCF[0][n8], ah[0], bh[n8][0], bh[n8][1]);
            mma_f32(accCF[1][n8], ah[1], bh[n8][0], bh[n8][1]);
        }
        #pragma unroll
        for (int n8 = 0; n8 < 4; ++n8) {
            mma_f16(accCH[0][n8], ah[0], bl[n8][0], bl[n8][1]);
            mma_f16(accCH[1][n8], ah[1], bl[n8][0], bl[n8][1]);
        }
        #pragma unroll
        for (int n8 = 0; n8 < 4; ++n8) {
            mma_f16(accCH[0][n8], al[0], bh[n8][0], bh[n8][1]);
            mma_f16(accCH[1][n8], al[1], bh[n8][0], bh[n8][1]);
        }
    }
    __syncthreads();   // stage-C smem reads done; reuse region for s-tile

    // ---- epilogue: combine + stage s tile, triu_sym on read, coalesced out
    float* ss = (float*)dynsm;   // [128][130]
    #pragma unroll
    for (int mt = 0; mt < 2; ++mt) {
        int x = wm * 32 + mt * 16 + (ln >> 2);
        #pragma unroll
        for (int nt = 0; nt < 4; ++nt) {
            int y = wn * 32 + nt * 8 + 2 * (ln & 3);
            float o[4]; comb4(accCF[mt][nt], accCH[mt][nt], o);
            ss[x * 130 + y]           = o[0];
            ss[x * 130 + y + 1]       = o[1];
            ss[(x + 8) * 130 + y]     = o[2];
            ss[(x + 8) * 130 + y + 1] = o[3];
        }
    }
    __syncthreads();

    bool dosym = (q != 0);
    float* o;
    if (q < 4) o = out + (size_t)q * 4194304 + (size_t)bz * 16384;
    else       o = &g_cp[(q - 4) * 2 + b][z][0][0];
    int r  = tid >> 2;            // 0..127
    int cb = (tid & 3) * 32;      // 0..96
    const float* pr2 = ss + r * 130;
    #pragma unroll
    for (int cc = 0; cc < 8; ++cc) {
        int c0 = cb + cc * 4;
        float4 v;
        v.x = (!dosym || r <= c0    ) ? pr2[c0]     : ss[(c0)     * 130 + r];
        v.y = (!dosym || r <= c0 + 1) ? pr2[c0 + 1] : ss[(c0 + 1) * 130 + r];
        v.z = (!dosym || r <= c0 + 2) ? pr2[c0 + 2] : ss[(c0 + 2) * 130 + r];
        v.w = (!dosym || r <= c0 + 3) ? pr2[c0 + 3] : ss[(c0 + 3) * 130 + r];
        *(float4*)(o + (size_t)r * 128 + c0) = v;
    }
}

// ---------------- co-parent permute: g_cp[t*2+b][z][x][y] -> out[b][x][y][z]
__global__ void k_cop(float* __restrict__ out)
{
    __shared__ float ts[32][33];
    int tile = blockIdx.x;
    int x    = blockIdx.y;
    int tb   = blockIdx.z;
    int z0 = (tile >> 2) * 32, y0 = (tile & 3) * 32;
    int tx = threadIdx.x, ty = threadIdx.y;
    const float* src = &g_cp[tb][0][x][0];
    #pragma unroll
    for (int i = ty; i < 32; i += 8)
        ts[i][tx] = src[(size_t)(z0 + i) * 16384 + y0 + tx];
    __syncthreads();
    float* dst = out + (size_t)(4 + (tb >> 1)) * 4194304 + (size_t)(tb & 1) * 2097152
               + (size_t)x * 16384;
    #pragma unroll
    for (int i = ty; i < 32; i += 8)
        dst[(size_t)(y0 + i) * 128 + z0 + tx] = ts[tx][i];
}

// ---------------------------------------------------------------------------
extern "C" void kernel_launch(void* const* d_in, const int* in_sizes, int n_in,
                              void* d_out, int out_size)
{
    const float* x      = (const float*)d_in[0];
    const float* W_sh   = (const float*)d_in[1];
    const float* b_sh   = (const float*)d_in[2];
    const float* W_st   = (const float*)d_in[3];
    const float* b_st   = (const float*)d_in[4];
    const float* W_p    = (const float*)d_in[5];
    const float* b_p    = (const float*)d_in[6];
    const float* T_pt   = (const float*)d_in[7];
    const float* T_ph   = (const float*)d_in[8];
    const float* T_phsib= (const float*)d_in[9];
    const float* T_ptsib= (const float*)d_in[10];
    const float* T_phcop= (const float*)d_in[11];
    const float* T_ptcop= (const float*)d_in[12];

    static bool attr_done = false;
    if (!attr_done) {
        cudaFuncSetAttribute(k_stageA,  cudaFuncAttributeMaxDynamicSharedMemorySize, 98304);
        cudaFuncSetAttribute(k_fusedBC, cudaFuncAttributeMaxDynamicSharedMemorySize, 192512);
        attr_done = true;
    }

    k_mlp   <<<dim3(BZ, 3), 160>>>(x, W_sh, b_sh, W_st, b_st, W_p, b_p);
    k_embimg<<<240, 256>>>();
    // q order: 0=T_ph 1=T_pt 2=T_phsib 3=T_ptsib 4=T_phcop 5=T_ptcop
    k_timg  <<<dim3(5, D, 6), 256>>>(T_ph, T_pt, T_phsib, T_ptsib, T_phcop, T_ptcop);
    k_stageA<<<dim3(200, 2, 6), 512, 98304>>>();
    k_fusedBC<<<dim3(BZ, 6), 512, 192512>>>((float*)d_out);
    k_cop   <<<dim3(16, 128, 4), dim3(32, 8)>>>((float*)d_out);
}

// round 11
// speedup vs baseline: 1.1291x; 1.1291x over previous
#include <cuda_runtime.h>
#include <cuda_bf16.h>
#include <cstdint>

#define D      150
#define Dp     160
#define NTOT   25600     // Dp*Dp, n = j*160 + i
#define BZ     256
#define DIN    1024

// ---------------- scratch (__device__ globals; zero-init; pads never written)
__device__ __align__(16) float g_emb[3][BZ][Dp];
__device__ __align__(16) __nv_bfloat16 g_eh[3][BZ][Dp];      // emb hi image
__device__ __align__(16) __nv_bfloat16 g_el[3][BZ][Dp];      // emb lo image
__device__ __align__(16) __nv_bfloat16 g_tbh[6][NTOT][Dp];   // T image [q][n][k] hi
__device__ __align__(16) __nv_bfloat16 g_tbl[6][NTOT][Dp];   // lo
__device__ __align__(16) __nv_bfloat16 g_wbh[6][BZ][Dp][Dp]; // w image [q][bz][j][i] hi
__device__ __align__(16) __nv_bfloat16 g_wbl[6][BZ][Dp][Dp]; // lo
__device__ __align__(16) float g_cp[4][128][128][128];       // co-parent staging

// q0 span_psh (no sym)  q1 span_pst (sym)  q2 ph_sib  q3 pt_sib
// q4 ph_cop  q5 pt_cop  (q4,q5 permuted out via g_cp + k_cop)
__constant__ int c_ZI[6] = {2,2,2,2,0,1};
__constant__ int c_XI[6] = {0,0,0,1,2,2};
__constant__ int c_YI[6] = {1,1,0,1,2,2};

// ---------------- low-level helpers ----------------------------------------
__device__ __forceinline__ uint32_t smem_u32(const void* p){
    uint32_t a;
    asm("{ .reg .u64 t; cvta.to.shared.u64 t, %1; cvt.u32.u64 %0, t; }" : "=r"(a) : "l"(p));
    return a;
}
__device__ __forceinline__ void split_pack(float a, float b, uint32_t& h, uint32_t& l){
    __nv_bfloat16 ah = __float2bfloat16(a), bh = __float2bfloat16(b);
    __nv_bfloat16 al = __float2bfloat16(a - __bfloat162float(ah));
    __nv_bfloat16 bl = __float2bfloat16(b - __bfloat162float(bh));
    h = (uint32_t)__bfloat16_as_ushort(ah) | ((uint32_t)__bfloat16_as_ushort(bh) << 16);
    l = (uint32_t)__bfloat16_as_ushort(al) | ((uint32_t)__bfloat16_as_ushort(bl) << 16);
}
__device__ __forceinline__ void mma16816(float* c, const uint32_t* a, uint32_t b0, uint32_t b1){
    asm volatile("mma.sync.aligned.m16n8k16.row.col.f32.bf16.bf16.f32 "
        "{%0,%1,%2,%3}, {%4,%5,%6,%7}, {%8,%9}, {%0,%1,%2,%3};"
        : "+f"(c[0]), "+f"(c[1]), "+f"(c[2]), "+f"(c[3])
        : "r"(a[0]), "r"(a[1]), "r"(a[2]), "r"(a[3]), "r"(b0), "r"(b1));
}
__device__ __forceinline__ void ldsm4(uint32_t* r, uint32_t a){
    asm volatile("ldmatrix.sync.aligned.m8n8.x4.shared.b16 {%0,%1,%2,%3}, [%4];"
        : "=r"(r[0]), "=r"(r[1]), "=r"(r[2]), "=r"(r[3]) : "r"(a));
}
__device__ __forceinline__ void cpa16(uint32_t s, const void* g){
    asm volatile("cp.async.cg.shared.global [%0], [%1], 16;" :: "r"(s), "l"(g));
}
#define CP_COMMIT() asm volatile("cp.async.commit_group;" ::: "memory")
#define CP_WAIT1()  asm volatile("cp.async.wait_group 1;" ::: "memory")
#define CP_WAIT0()  asm volatile("cp.async.wait_group 0;" ::: "memory")

// 32B-row layout (k16 chunks): 2x16B units/row, XOR swizzle (R7-proven)
__device__ __forceinline__ uint32_t swz(int row, int u){
    return (uint32_t)(row * 32 + (((u ^ (row >> 2)) & 1) << 4));
}
__device__ __forceinline__ uint32_t lds_addr(uint32_t base, int r0, int ln){
    int g = ln >> 3;
    int row = r0 + ((g & 1) << 3) + (ln & 7);
    return base + swz(row, g >> 1);
}
// 64B-row layout (k32 chunks), R9-proven
__device__ __forceinline__ uint32_t swz64(int row, int u){
    return (uint32_t)(row * 64 + 16 * ((u ^ (row >> 1)) & 3));
}
__device__ __forceinline__ uint32_t a64(uint32_t base, int r0, int ln, int c){
    int g = ln >> 3;
    int row = r0 + ((g & 1) << 3) + (ln & 7);
    return base + swz64(row, 2 * c + (g >> 1));
}
// 320B-row image layout (v), R7-proven
__device__ __forceinline__ uint32_t voff(int row, int j){
    return (uint32_t)(row * 320 + 16 * ((j >> 3) ^ ((row >> 1) & 3)) + (j & 7) * 2);
}
__device__ __forceinline__ uint32_t vuoff(int row, int u){
    return (uint32_t)(row * 320 + 16 * (u ^ ((row >> 1) & 3)));
}
__device__ __forceinline__ uint32_t ldsV(uint32_t base, int r0, int ln, int u0){
    int g = ln >> 3;
    int row = r0 + ((g & 1) << 3) + (ln & 7);
    return base + vuoff(row, u0 + (g >> 1));
}
// ILP-4 split-major 12-MMA block
#define MMA_BLK(t00, t01, t10, t11, ah, al, bh, bl) do { \
    mma16816(t00, ah[0], bh[0], bh[2]); \
    mma16816(t01, ah[0], bh[1], bh[3]); \
    mma16816(t10, ah[1], bh[0], bh[2]); \
    mma16816(t11, ah[1], bh[1], bh[3]); \
    mma16816(t00, ah[0], bl[0], bl[2]); \
    mma16816(t01, ah[0], bl[1], bl[3]); \
    mma16816(t10, ah[1], bl[0], bl[2]); \
    mma16816(t11, ah[1], bl[1], bl[3]); \
    mma16816(t00, al[0], bh[0], bh[2]); \
    mma16816(t01, al[0], bh[1], bh[3]); \
    mma16816(t10, al[1], bh[0], bh[2]); \
    mma16816(t11, al[1], bh[1], bh[3]); \
} while(0)

// ---------------- MLP -------------------------------------------------------
__global__ void k_mlp(const float* __restrict__ x,
                      const float* __restrict__ W0, const float* __restrict__ b0,
                      const float* __restrict__ W1, const float* __restrict__ b1,
                      const float* __restrict__ W2, const float* __restrict__ b2)
{
    int row = blockIdx.x, e = blockIdx.y;
    const float* W  = (e == 0) ? W0 : (e == 1) ? W1 : W2;
    const float* bb = (e == 0) ? b0 : (e == 1) ? b1 : b2;
    __shared__ float xs[DIN];
    int tid = threadIdx.x;
    for (int k = tid; k < DIN; k += 160) xs[k] = x[row * DIN + k];
    __syncthreads();
    if (tid < D) {
        float acc = bb[tid];
        #pragma unroll 8
        for (int k = 0; k < DIN; ++k) acc += xs[k] * W[k * D + tid];
        g_emb[e][row][tid] = (acc >= 0.f) ? acc : 0.1f * acc;
    }
}

// ---------------- emb -> split bf16 images ---------------------------------
__global__ void k_embimg()
{
    int idx = blockIdx.x * 256 + threadIdx.x;
    if (idx >= 3 * 256 * 80) return;
    int e = idx / 20480, rem = idx % 20480;
    int row = rem / 80, kp = rem % 80;
    uint32_t h, l;
    split_pack(g_emb[e][row][2*kp], g_emb[e][row][2*kp+1], h, l);
    *(uint32_t*)&g_eh[e][row][2*kp] = h;
    *(uint32_t*)&g_el[e][row][2*kp] = l;
}

// ---------------- T[i][k][j] -> TB[q][(j*160+i)][k] hi/lo -------------------
__global__ void k_timg(const float* __restrict__ T0, const float* __restrict__ T1,
                       const float* __restrict__ T2, const float* __restrict__ T3,
                       const float* __restrict__ T4, const float* __restrict__ T5)
{
    int q = blockIdx.z, i = blockIdx.y, j0 = blockIdx.x * 32;
    const float* T = (q==0)?T0:(q==1)?T1:(q==2)?T2:(q==3)?T3:(q==4)?T4:T5;
    __shared__ float ts[32][152];
    int tid = threadIdx.x;
    for (int t = tid; t < 150 * 32; t += 256) {
        int k = t >> 5, j = t & 31;
        if (j0 + j < D) ts[j][k] = T[(i * D + k) * D + j0 + j];
    }
    __syncthreads();
    for (int t = tid; t < 32 * 75; t += 256) {
        int j = t / 75, kp = t % 75;
        if (j0 + j < D) {
            uint32_t h, l;
            split_pack(ts[j][2*kp], ts[j][2*kp+1], h, l);
            int n = (j0 + j) * Dp + i;
            *(uint32_t*)&g_tbh[q][n][2*kp] = h;
            *(uint32_t*)&g_tbl[q][n][2*kp] = l;
        }
    }
}

// ---------------- stage A: w = Z . TB^T, k32 chunks (R9 exact) --------------
__global__ void __launch_bounds__(256, 2) k_stageA()
{
    extern __shared__ __align__(16) unsigned char smA[];   // 3 x 32768
    uint32_t sb = smem_u32(smA);
    int q = blockIdx.z, m0 = blockIdx.y * 128, n0 = blockIdx.x * 128;
    int tid = threadIdx.x, w = tid >> 5, ln = tid & 31;
    int wm = w & 3, wn = w >> 2;
    int zi = c_ZI[q];

    int pr = tid >> 2, pu = tid & 3;
    uint32_t sw0 = swz64(pr, pu);
    const __nv_bfloat16* gpA[4];
    gpA[0] = &g_eh[zi][0][0]  + (size_t)(m0 + pr) * Dp + pu * 8;
    gpA[1] = &g_el[zi][0][0]  + (size_t)(m0 + pr) * Dp + pu * 8;
    gpA[2] = &g_tbh[q][0][0]  + (size_t)(n0 + pr) * Dp + pu * 8;
    gpA[3] = &g_tbl[q][0][0]  + (size_t)(n0 + pr) * Dp + pu * 8;

    float acc[2][8][4];
    #pragma unroll
    for (int a = 0; a < 2; ++a)
        #pragma unroll
        for (int b = 0; b < 8; ++b)
            #pragma unroll
            for (int c = 0; c < 4; ++c) acc[a][b][c] = 0.f;

    #define PREF_A(slot, kc) do { \
        if ((kc) < Dp) { \
            uint32_t db = sb + (slot) * 32768 + sw0; \
            _Pragma("unroll") \
            for (int a = 0; a < 4; ++a) { \
                cpa16(db + a * 8192,        gpA[a] + (kc)); \
                cpa16(db + a * 8192 + 4096, gpA[a] + 64 * Dp + (kc)); \
            } \
        } \
        CP_COMMIT(); \
    } while(0)

    PREF_A(0, 0);
    PREF_A(1, 32);
    for (int ks = 0; ks < 5; ++ks) {
        CP_WAIT1();
        __syncthreads();
        PREF_A((ks + 2) % 3, (ks + 2) * 32);
        uint32_t base = sb + (ks % 3) * 32768;
        #pragma unroll
        for (int c = 0; c < 2; ++c) {
            uint32_t ah[2][4], al[2][4];
            #pragma unroll
            for (int mt = 0; mt < 2; ++mt) {
                ldsm4(ah[mt], a64(base,        wm * 32 + mt * 16, ln, c));
                ldsm4(al[mt], a64(base + 8192, wm * 32 + mt * 16, ln, c));
            }
            #pragma unroll
            for (int p = 0; p < 4; ++p) {
                uint32_t bh[4], bl[4];
                ldsm4(bh, a64(base + 16384, wn * 64 + p * 16, ln, c));
                ldsm4(bl, a64(base + 24576, wn * 64 + p * 16, ln, c));
                MMA_BLK(acc[0][2*p], acc[0][2*p+1], acc[1][2*p], acc[1][2*p+1], ah, al, bh, bl);
            }
        }
    }
    #undef PREF_A

    __nv_bfloat16* WH = &g_wbh[0][0][0][0];
    __nv_bfloat16* WL = &g_wbl[0][0][0][0];
    int yb = 2 * (ln & 3);
    #pragma unroll
    for (int mt = 0; mt < 2; ++mt) {
        int mA = m0 + wm * 32 + mt * 16 + (ln >> 2);
        #pragma unroll
        for (int nt = 0; nt < 8; ++nt) {
            int n = n0 + wn * 64 + nt * 8 + yb;
            size_t off0 = ((size_t)(q * BZ + mA)) * 25600 + n;
            size_t off1 = off0 + (size_t)8 * 25600;
            uint32_t h, l;
            split_pack(acc[mt][nt][0], acc[mt][nt][1], h, l);
            *(uint32_t*)(WH + off0) = h; *(uint32_t*)(WL + off0) = l;
            split_pack(acc[mt][nt][2], acc[mt][nt][3], h, l);
            *(uint32_t*)(WH + off1) = h; *(uint32_t*)(WL + off1) = l;
        }
    }
}

// ---------------- fused B+C per (q,bz): 256 thr, 2 CTA/SM -------------------
// stage B: k16 3-slot at [0,55296), warps 4m x 2n, tile 32x80
// v images (hi/lo) at [0,81920)  (written after stage B)
// Y chunks streamed per-k16, 3 slots x 8192 at [81920,106496)
// stage C: warps mapped (tm = w<4 ? w : 7-w, tn = w>>2), tile 32x64;
//          for q>=1 skip strictly-lower 16-col blocks (pb < pb0)
// epilogue: s-tile ss[128][130] at [0,66560), triu_sym on read
__device__ __forceinline__ void prefB(uint32_t sb, int slot, int k0, int tid,
    const __nv_bfloat16* Xh, const __nv_bfloat16* Xl,
    const __nv_bfloat16* Wh, const __nv_bfloat16* Wl)
{
    if (k0 < Dp) {
        for (int t = tid; t < 1152; t += 256) {
            uint32_t dst; const __nv_bfloat16* g;
            if (t < 512) {
                int img = t >> 8, rr = (t >> 1) & 127, u = t & 1;
                dst = sb + slot * 18432 + img * 4096 + swz(rr, u);
                g = (img ? Xl : Xh) + (size_t)rr * Dp + k0 + u * 8;
            } else {
                int t2 = t - 512;
                int img = t2 / 320, r2 = t2 - img * 320;
                int rr = r2 >> 1, u = r2 & 1;
                dst = sb + slot * 18432 + 8192 + img * 5120 + swz(rr, u);
                g = (img ? Wl : Wh) + (size_t)rr * Dp + k0 + u * 8;
            }
            cpa16(dst, g);
        }
    }
    CP_COMMIT();
}

__global__ void __launch_bounds__(256, 2) k_fusedBC(float* __restrict__ out)
{
    extern __shared__ __align__(16) unsigned char dynsm[];
    uint32_t sb = smem_u32(dynsm);
    int q = blockIdx.y, bz = blockIdx.x, b = bz >> 7, z = bz & 127;
    int tid = threadIdx.x, w = tid >> 5, ln = tid & 31;
    int wm = w & 3, wn = w >> 2;                    // stage B mapping (4x2)
    int tm = (w < 4) ? w : 7 - w, tn = w >> 2;      // stage C mapping (balanced)
    int pb0 = (q == 0) ? 0 : max(0, min(4, 2 * tm - 4 * tn));

    const __nv_bfloat16 *Xh = &g_eh[c_XI[q]][b*128][0], *Xl = &g_el[c_XI[q]][b*128][0];
    const __nv_bfloat16 *Wh = &g_wbh[q][bz][0][0],      *Wl = &g_wbl[q][bz][0][0];
    const __nv_bfloat16 *Yh = &g_eh[c_YI[q]][b*128][0], *Yl = &g_el[c_YI[q]][b*128][0];

    // ---- stage B (warp tile 32x80, k16, 3-slot, 1 sync/iter)
    float accB[2][10][4];
    #pragma unroll
    for (int mt = 0; mt < 2; ++mt)
        #pragma unroll
        for (int i = 0; i < 10; ++i)
            #pragma unroll
            for (int c = 0; c < 4; ++c) accB[mt][i][c] = 0.f;

    prefB(sb, 0, 0,  tid, Xh, Xl, Wh, Wl);
    prefB(sb, 1, 16, tid, Xh, Xl, Wh, Wl);
    for (int ks = 0; ks < 10; ++ks) {
        CP_WAIT1();
        __syncthreads();
        prefB(sb, (ks + 2) % 3, (ks + 2) * 16, tid, Xh, Xl, Wh, Wl);
        uint32_t base = sb + (ks % 3) * 18432;
        uint32_t ah[2][4], al[2][4];
        #pragma unroll
        for (int mt = 0; mt < 2; ++mt) {
            ldsm4(ah[mt], lds_addr(base,        wm * 32 + mt * 16, ln));
            ldsm4(al[mt], lds_addr(base + 4096, wm * 32 + mt * 16, ln));
        }
        #pragma unroll
        for (int p = 0; p < 5; ++p) {
            uint32_t bh[4], bl[4];
            ldsm4(bh, lds_addr(base + 8192,  wn * 80 + p * 16, ln));
            ldsm4(bl, lds_addr(base + 13312, wn * 80 + p * 16, ln));
            MMA_BLK(accB[0][2*p], accB[0][2*p+1], accB[1][2*p], accB[1][2*p+1], ah, al, bh, bl);
        }
    }
    CP_WAIT0();
    __syncthreads();   // stage-B smem reads done; region reused for v images

    // ---- Y chunk prefetch macro (k16 chunks, 3 slots at [81920,106496))
    #define PREF_Y(slot, kc) do { \
        if ((kc) < Dp) { \
            int t = tid; \
            _Pragma("unroll") \
            for (int it = 0; it < 2; ++it, t += 256) { \
                int img = t >> 8, r2 = t & 255; \
                int row = r2 >> 1, u = r2 & 1; \
                cpa16(sb + 81920 + (slot) * 8192 + img * 4096 + swz(row, u), \
                      (img ? Yl : Yh) + (size_t)row * Dp + (kc) + u * 8); \
            } \
        } \
        CP_COMMIT(); \
    } while(0)

    PREF_Y(0, 0);
    PREF_Y(1, 16);

    // ---- v -> split-bf16 smem images at [0,81920)  (hi@0, lo@40960)
    #pragma unroll
    for (int mt = 0; mt < 2; ++mt) {
        #pragma unroll
        for (int n8 = 0; n8 < 10; ++n8) {
            int j  = wn * 80 + n8 * 8 + 2 * (ln & 3);
            int x1 = wm * 32 + mt * 16 + (ln >> 2);
            uint32_t h, l;
            split_pack(accB[mt][n8][0], accB[mt][n8][1], h, l);
            *(uint32_t*)(dynsm + voff(x1, j))         = h;
            *(uint32_t*)(dynsm + 40960 + voff(x1, j)) = l;
            split_pack(accB[mt][n8][2], accB[mt][n8][3], h, l);
            *(uint32_t*)(dynsm + voff(x1 + 8, j))         = h;
            *(uint32_t*)(dynsm + 40960 + voff(x1 + 8, j)) = l;
        }
    }

    // ---- stage C (warp tile 32x64, A from v-images, B from streamed Y)
    float accC[2][8][4];
    #pragma unroll
    for (int mt = 0; mt < 2; ++mt)
        #pragma unroll
        for (int i = 0; i < 8; ++i)
            #pragma unroll
            for (int c = 0; c < 4; ++c) accC[mt][i][c] = 0.f;

    for (int kk = 0; kk < 10; ++kk) {
        CP_WAIT1();
        __syncthreads();          // (first iter also publishes v images)
        PREF_Y((kk + 2) % 3, (kk + 2) * 16);
        uint32_t ybase = sb + 81920 + (kk % 3) * 8192;
        int u0 = kk * 2;
        uint32_t ah[2][4], al[2][4];
        #pragma unroll
        for (int mt = 0; mt < 2; ++mt) {
            ldsm4(ah[mt], ldsV(sb,         tm * 32 + mt * 16, ln, u0));
            ldsm4(al[mt], ldsV(sb + 40960, tm * 32 + mt * 16, ln, u0));
        }
        #pragma unroll
        for (int pb = 0; pb < 4; ++pb) {
            if (pb >= pb0) {
                uint32_t bh[4], bl[4];
                ldsm4(bh, lds_addr(ybase,        tn * 64 + pb * 16, ln));
                ldsm4(bl, lds_addr(ybase + 4096, tn * 64 + pb * 16, ln));
                MMA_BLK(accC[0][2*pb], accC[0][2*pb+1], accC[1][2*pb], accC[1][2*pb+1],
                        ah, al, bh, bl);
            }
        }
    }
    #undef PREF_Y
    CP_WAIT0();
    __syncthreads();   // stage-C smem reads done; reuse region for s-tile

    // ---- epilogue: stage s tile, triu_sym on read, coalesced out
    float* ss = (float*)dynsm;   // [128][130]
    #pragma unroll
    for (int mt = 0; mt < 2; ++mt) {
        int x = tm * 32 + mt * 16 + (ln >> 2);
        #pragma unroll
        for (int nt = 0; nt < 8; ++nt) {
            int y = tn * 64 + nt * 8 + 2 * (ln & 3);
            ss[x * 130 + y]           = accC[mt][nt][0];
            ss[x * 130 + y + 1]       = accC[mt][nt][1];
            ss[(x + 8) * 130 + y]     = accC[mt][nt][2];
            ss[(x + 8) * 130 + y + 1] = accC[mt][nt][3];
        }
    }
    __syncthreads();

    bool dosym = (q != 0);
    float* o;
    if (q < 4) o = out + (size_t)q * 4194304 + (size_t)bz * 16384;
    else       o = &g_cp[(q - 4) * 2 + b][z][0][0];
    int c0 = ln * 4;
    #pragma unroll
    for (int rr = 0; rr < 16; ++rr) {
        int r = w * 16 + rr;
        const float* pr2 = ss + r * 130;
        float4 v;
        v.x = (!dosym || r <= c0    ) ? pr2[c0]     : ss[(c0)     * 130 + r];
        v.y = (!dosym || r <= c0 + 1) ? pr2[c0 + 1] : ss[(c0 + 1) * 130 + r];
        v.z = (!dosym || r <= c0 + 2) ? pr2[c0 + 2] : ss[(c0 + 2) * 130 + r];
        v.w = (!dosym || r <= c0 + 3) ? pr2[c0 + 3] : ss[(c0 + 3) * 130 + r];
        *(float4*)(o + (size_t)r * 128 + c0) = v;
    }
}

// ---------------- co-parent permute: g_cp[t*2+b][z][x][y] -> out[b][x][y][z]
__global__ void k_cop(float* __restrict__ out)
{
    __shared__ float ts[32][33];
    int tile = blockIdx.x;
    int x    = blockIdx.y;
    int tb   = blockIdx.z;
    int z0 = (tile >> 2) * 32, y0 = (tile & 3) * 32;
    int tx = threadIdx.x, ty = threadIdx.y;
    const float* src = &g_cp[tb][0][x][0];
    #pragma unroll
    for (int i = ty; i < 32; i += 8)
        ts[i][tx] = src[(size_t)(z0 + i) * 16384 + y0 + tx];
    __syncthreads();
    float* dst = out + (size_t)(4 + (tb >> 1)) * 4194304 + (size_t)(tb & 1) * 2097152
               + (size_t)x * 16384;
    #pragma unroll
    for (int i = ty; i < 32; i += 8)
        dst[(size_t)(y0 + i) * 128 + z0 + tx] = ts[tx][i];
}

// ---------------------------------------------------------------------------
extern "C" void kernel_launch(void* const* d_in, const int* in_sizes, int n_in,
                              void* d_out, int out_size)
{
    const float* x      = (const float*)d_in[0];
    const float* W_sh   = (const float*)d_in[1];
    const float* b_sh   = (const float*)d_in[2];
    const float* W_st   = (const float*)d_in[3];
    const float* b_st   = (const float*)d_in[4];
    const float* W_p    = (const float*)d_in[5];
    const float* b_p    = (const float*)d_in[6];
    const float* T_pt   = (const float*)d_in[7];
    const float* T_ph   = (const float*)d_in[8];
    const float* T_phsib= (const float*)d_in[9];
    const float* T_ptsib= (const float*)d_in[10];
    const float* T_phcop= (const float*)d_in[11];
    const float* T_ptcop= (const float*)d_in[12];

    static bool attr_done = false;
    if (!attr_done) {
        cudaFuncSetAttribute(k_stageA,  cudaFuncAttributeMaxDynamicSharedMemorySize, 98304);
        cudaFuncSetAttribute(k_fusedBC, cudaFuncAttributeMaxDynamicSharedMemorySize, 106496);
        attr_done = true;
    }

    k_mlp   <<<dim3(BZ, 3), 160>>>(x, W_sh, b_sh, W_st, b_st, W_p, b_p);
    k_embimg<<<240, 256>>>();
    // q order: 0=T_ph 1=T_pt 2=T_phsib 3=T_ptsib 4=T_phcop 5=T_ptcop
    k_timg  <<<dim3(5, D, 6), 256>>>(T_ph, T_pt, T_phsib, T_ptsib, T_phcop, T_ptcop);
    k_stageA<<<dim3(200, 2, 6), 256, 98304>>>();
    k_fusedBC<<<dim3(BZ, 6), 256, 106496>>>((float*)d_out);
    k_cop   <<<dim3(16, 128, 4), dim3(32, 8)>>>((float*)d_out);
}